// round 14
// baseline (speedup 1.0000x reference)
#include <cuda_runtime.h>
#include <math.h>
#include <stdint.h>

#define NROWS 65536
#define D 256
#define NC 1000
#define NCP 1024
#define MROWS 128
#define NTILES (NROWS / MROWS)   // 512
#define GRID 296                 // 2 CTAs/SM x 148 SMs, all co-resident
#define TPB 256
#define NTHREADS (GRID * TPB)    // 75776
#define EBP 132    // Ebf pitch in words (132%32=4 -> conflict-free A frags)
#define MBP 72     // Msbf pitch in words (72%32=8 -> conflict-free B frags)
#define NREP 16    // g_sums replicas

// ---------------- device scratch ----------------
__device__ float g_sums[NREP * NC * D];
__device__ float g_counts[NREP * NC];
__device__ float g_chat[NCP * D];
__device__ float g_v[D];
__device__ float g_M[D * D];
__device__ uint32_t g_Mbf[(D / 2) * D];   // packed bf16 pairs: [kpair][n]
__device__ float g_loss;
__device__ unsigned int g_bar;            // monotone barrier counter

__device__ __forceinline__ uint32_t pack_bf16(float lo, float hi) {
    uint32_t r;
    asm("cvt.rn.bf16x2.f32 %0, %1, %2;" : "=r"(r) : "f"(hi), "f"(lo));
    return r;
}
__device__ __forceinline__ float2 unpack_bf16(uint32_t w) {
    float2 f;
    f.x = __uint_as_float(w << 16);
    f.y = __uint_as_float(w & 0xffff0000u);
    return f;
}
__device__ __forceinline__ void red_v4(float* p, float a, float b, float c, float d) {
    asm volatile("red.global.add.v4.f32 [%0], {%1,%2,%3,%4};"
                 :: "l"(p), "f"(a), "f"(b), "f"(c), "f"(d) : "memory");
}

// Grid-wide barrier. All GRID CTAs are co-resident (occ 2 enforced), so the
// spin cannot deadlock. Counter is monotone across launches; target rounds
// up to the next multiple of GRID, which is launch-invariant.
__device__ __forceinline__ void grid_barrier() {
    __syncthreads();
    if (threadIdx.x == 0) {
        __threadfence();
        unsigned int old = atomicAdd(&g_bar, 1u) + 1u;
        unsigned int target = ((old + GRID - 1u) / GRID) * GRID;
        while (*((volatile unsigned int*)&g_bar) < target) __nanosleep(64);
        __threadfence();
    }
    __syncthreads();
}

// ---------------------------------------------------------------------------
__global__ __launch_bounds__(TPB, 2)
void k_fused(const float* __restrict__ emb, const int* __restrict__ labels,
             float* __restrict__ out) {
    extern __shared__ float sh[];
    uint32_t* Ebf  = (uint32_t*)sh;            // 128*EBP = 16896 words
    uint32_t* Msbf = Ebf + MROWS * EBP;        // 128*MBP = 9216 words
    float* vsh   = (float*)(Msbf + 128 * MBP); // 256
    float* s2row = vsh + 256;                  // 128
    float* redA  = s2row + 128;                // 256
    float* redB  = redA + 256;                 // 256
    float* redC  = redB + 256;                 // 256
    int*   labsh = (int*)(redC + 256);         // 128
    float* lsum  = (float*)(labsh + 128);      // 8

    int t = threadIdx.x;
    int bid = blockIdx.x;
    int gtid = bid * TPB + t;
    int lane = t & 31, w = t >> 5;
    int g = lane >> 2, j = lane & 3;
    int rbw = (w & 3) * 32;
    int nb = (w >> 2) * 32;

    // ---------------- P0: zero scratch ----------------
    {
        const float4 z4 = make_float4(0.f, 0.f, 0.f, 0.f);
        for (int i = gtid; i < NREP * NC * D / 4; i += NTHREADS)
            ((float4*)g_sums)[i] = z4;
        for (int i = gtid; i < D * D / 4; i += NTHREADS)
            ((float4*)g_M)[i] = z4;
        if (gtid < NREP * NC / 4) ((float4*)g_counts)[gtid] = z4;
        if (gtid < (NCP - NC) * D / 4)                  // zero g_chat padding rows
            ((float4*)(g_chat + NC * D))[gtid] = z4;
        if (gtid < D / 4) ((float4*)g_v)[gtid] = z4;
        if (gtid == 0) g_loss = 0.f;
    }
    grid_barrier();

    // ---------------- P1: normalize + class sums ----------------
    {
        int gw = bid * 8 + w;                  // 2368 warps
        for (int row = gw; row < NROWS; row += GRID * 8) {
            const float* e = emb + (size_t)row * D;
            float4 x0 = *(const float4*)(e + lane * 4);
            float4 x1 = *(const float4*)(e + 128 + lane * 4);
            float ss = x0.x * x0.x + x0.y * x0.y + x0.z * x0.z + x0.w * x0.w
                     + x1.x * x1.x + x1.y * x1.y + x1.z * x1.z + x1.w * x1.w;
            #pragma unroll
            for (int off = 16; off; off >>= 1)
                ss += __shfl_xor_sync(0xffffffffu, ss, off);
            float rn = 1.f / fmaxf(sqrtf(ss), 1e-12f);
            int lab = labels[row];
            int rep = (row >> 3) & (NREP - 1);
            float* dst = g_sums + ((size_t)rep * NC + lab) * D;
            red_v4(dst + lane * 4,       x0.x * rn, x0.y * rn, x0.z * rn, x0.w * rn);
            red_v4(dst + 128 + lane * 4, x1.x * rn, x1.y * rn, x1.z * rn, x1.w * rn);
            if (lane == 0) atomicAdd(&g_counts[rep * NC + lab], 1.f);
        }
    }
    grid_barrier();

    // ---------------- P2: centers -> chat, v ----------------
    {
        __shared__ float wsum[8];
        __shared__ float denom_s;
        for (int c = bid; c < NC; c += GRID) {
            float cnt = 0.f, s = 0.f;
            #pragma unroll
            for (int rp = 0; rp < NREP; rp++) {
                cnt += __ldcg(&g_counts[rp * NC + c]);
                s += __ldcg(&g_sums[((size_t)rp * NC + c) * D + t]);
            }
            float center = s / fmaxf(cnt, 1.f);
            float ss = center * center;
            #pragma unroll
            for (int off = 16; off; off >>= 1)
                ss += __shfl_xor_sync(0xffffffffu, ss, off);
            if (lane == 0) wsum[w] = ss;
            __syncthreads();
            if (t == 0) {
                float tot = 0.f;
                #pragma unroll
                for (int k = 0; k < 8; k++) tot += wsum[k];
                denom_s = fmaxf(sqrtf(tot), 1e-8f);
            }
            __syncthreads();
            float ch = center / denom_s;
            g_chat[(size_t)c * D + t] = ch;
            atomicAdd(&g_v[t], ch);
            __syncthreads();
        }
    }
    grid_barrier();

    // ---------------- P3: M = Chat^T Chat (16 K-splits) ----------------
    {
        float* As = sh;                        // overlay on Ebf region
        float* Bs = sh + 16 * 64;
        for (int vb = bid; vb < 256; vb += GRID) {   // each CTA does <= 1
            int cb = (vb & 3) * 64;
            int rb = ((vb >> 2) & 3) * 64;
            int k0 = (vb >> 4) * 64;
            float acc[4][4] = {};
            int tx = t & 15, ty = t >> 4;
            #pragma unroll 1
            for (int kc = 0; kc < 4; kc++) {
                __syncthreads();
                {
                    int kk = t >> 4, c4 = (t & 15) << 2;
                    const float* src = g_chat + (size_t)(k0 + kc * 16 + kk) * D;
                    *(float4*)&As[kk * 64 + c4] = __ldcg((const float4*)(src + rb + c4));
                    *(float4*)&Bs[kk * 64 + c4] = __ldcg((const float4*)(src + cb + c4));
                }
                __syncthreads();
                #pragma unroll
                for (int kk = 0; kk < 16; kk++) {
                    float a[4], b[4];
                    *(float4*)a = *(float4*)&As[kk * 64 + ty * 4];
                    *(float4*)b = *(float4*)&Bs[kk * 64 + tx * 4];
                    #pragma unroll
                    for (int i = 0; i < 4; i++)
                        #pragma unroll
                        for (int jj = 0; jj < 4; jj++)
                            acc[i][jj] += a[i] * b[jj];
                }
            }
            #pragma unroll
            for (int i = 0; i < 4; i++)
                #pragma unroll
                for (int jj = 0; jj < 4; jj++)
                    atomicAdd(&g_M[(size_t)(rb + ty * 4 + i) * D + cb + tx * 4 + jj],
                              acc[i][jj]);
        }
    }
    grid_barrier();

    // ---------------- P4: pack M to bf16 pairs ----------------
    if (gtid < (D / 2) * D) {
        int kp = gtid >> 8, n = gtid & 255;
        g_Mbf[gtid] = pack_bf16(__ldcg(&g_M[(size_t)(2 * kp) * D + n]),
                                __ldcg(&g_M[(size_t)(2 * kp + 1) * D + n]));
    }
    grid_barrier();

    // ---------------- P5: main tile loop (R7 body) ----------------
    vsh[t] = __ldcg(&g_v[t]);
    float li_acc = 0.f;

    #pragma unroll 1
    for (int tile = bid; tile < NTILES; tile += GRID) {
        int row0 = tile * MROWS;
        __syncthreads();   // protect Ebf/vsh vs prior epilogue reads

        #pragma unroll
        for (int i = 0; i < 32; i++) {
            int idx = t + i * TPB;
            int r = idx >> 6, c = (idx & 63) << 2;
            float4 x = *(const float4*)(emb + (size_t)(row0 + r) * D + c);
            uint2 p;
            p.x = pack_bf16(x.x, x.y);
            p.y = pack_bf16(x.z, x.w);
            *(uint2*)(Ebf + r * EBP + (c >> 1)) = p;
        }
        if (t < 128) labsh[t] = labels[row0 + t];
        if (t < 128) s2row[t] = 0.f;

        float s2p[4] = {0.f, 0.f, 0.f, 0.f};

        #pragma unroll 1
        for (int dc = 0; dc < 4; dc++) {
            __syncthreads();
            #pragma unroll
            for (int i = 0; i < 8; i++) {
                int idx = t + i * TPB;         // 0..2047 uint4 slots
                int kp = idx >> 4, c4 = (idx & 15) << 2;
                *(uint4*)(Msbf + kp * MBP + c4) =
                    __ldcg((const uint4*)(g_Mbf + kp * 256 + dc * 64 + c4));
            }
            __syncthreads();

            float acc[2][4][4] = {};
            #pragma unroll 2
            for (int ks = 0; ks < 16; ks++) {
                int kp = ks * 8;
                uint32_t a[2][4];
                #pragma unroll
                for (int mt = 0; mt < 2; mt++) {
                    const uint32_t* ar = Ebf + (rbw + mt * 16 + g) * EBP + kp + j;
                    a[mt][0] = ar[0];
                    a[mt][1] = ar[8 * EBP];
                    a[mt][2] = ar[4];
                    a[mt][3] = ar[8 * EBP + 4];
                }
                #pragma unroll
                for (int nt = 0; nt < 4; nt++) {
                    uint32_t b0 = Msbf[(kp + j) * MBP + nb + nt * 8 + g];
                    uint32_t b1 = Msbf[(kp + 4 + j) * MBP + nb + nt * 8 + g];
                    #pragma unroll
                    for (int mt = 0; mt < 2; mt++) {
                        asm volatile(
                            "mma.sync.aligned.m16n8k16.row.col.f32.bf16.bf16.f32 "
                            "{%0,%1,%2,%3}, {%4,%5,%6,%7}, {%8,%9}, {%0,%1,%2,%3};"
                            : "+f"(acc[mt][nt][0]), "+f"(acc[mt][nt][1]),
                              "+f"(acc[mt][nt][2]), "+f"(acc[mt][nt][3])
                            : "r"(a[mt][0]), "r"(a[mt][1]), "r"(a[mt][2]), "r"(a[mt][3]),
                              "r"(b0), "r"(b1));
                    }
                }
            }
            #pragma unroll
            for (int mt = 0; mt < 2; mt++) {
                #pragma unroll
                for (int nt = 0; nt < 4; nt++) {
                    int wc = (dc * 64 + nb + nt * 8) / 2 + j;
                    int r0 = rbw + mt * 16 + g;
                    float2 e0 = unpack_bf16(Ebf[r0 * EBP + wc]);
                    float2 e1 = unpack_bf16(Ebf[(r0 + 8) * EBP + wc]);
                    s2p[mt * 2 + 0] += acc[mt][nt][0] * e0.x + acc[mt][nt][1] * e0.y;
                    s2p[mt * 2 + 1] += acc[mt][nt][2] * e1.x + acc[mt][nt][3] * e1.y;
                }
            }
        }

        #pragma unroll
        for (int i = 0; i < 4; i++) {
            float v = s2p[i];
            v += __shfl_xor_sync(0xffffffffu, v, 1);
            v += __shfl_xor_sync(0xffffffffu, v, 2);
            s2p[i] = v;
        }
        if (j == 0) {
            atomicAdd(&s2row[rbw + g],      s2p[0]);
            atomicAdd(&s2row[rbw + g + 8],  s2p[1]);
            atomicAdd(&s2row[rbw + 16 + g], s2p[2]);
            atomicAdd(&s2row[rbw + 24 + g], s2p[3]);
        }

        {
            int r = t & 127, q = t >> 7;
            const uint32_t* er = Ebf + r * EBP + q * 64;
            const float* vr = vsh + q * 128;
            const float* cr = g_chat + (size_t)labsh[r] * D + q * 128;
            float ss = 0.f, s1 = 0.f, sl = 0.f;
            #pragma unroll
            for (int m = 0; m < 16; m++) {
                uint4 ew = *(const uint4*)(er + m * 4);
                float2 e0 = unpack_bf16(ew.x), e1 = unpack_bf16(ew.y);
                float2 e2 = unpack_bf16(ew.z), e3 = unpack_bf16(ew.w);
                float4 v0 = *(const float4*)(vr + m * 8);
                float4 v1 = *(const float4*)(vr + m * 8 + 4);
                float4 c0 = __ldcg((const float4*)(cr + m * 8));
                float4 c1 = __ldcg((const float4*)(cr + m * 8 + 4));
                ss += e0.x * e0.x + e0.y * e0.y + e1.x * e1.x + e1.y * e1.y
                    + e2.x * e2.x + e2.y * e2.y + e3.x * e3.x + e3.y * e3.y;
                s1 += e0.x * v0.x + e0.y * v0.y + e1.x * v0.z + e1.y * v0.w
                    + e2.x * v1.x + e2.y * v1.y + e3.x * v1.z + e3.y * v1.w;
                sl += e0.x * c0.x + e0.y * c0.y + e1.x * c0.z + e1.y * c0.w
                    + e2.x * c1.x + e2.y * c1.y + e3.x * c1.z + e3.y * c1.w;
            }
            redA[q * 128 + r] = ss;
            redB[q * 128 + r] = s1;
            redC[q * 128 + r] = sl;
        }
        __syncthreads();

        if (t < 128) {
            int r = t;
            float ss = redA[r] + redA[128 + r];
            float s1 = redB[r] + redB[128 + r];
            float sl = redC[r] + redC[128 + r];
            float rn = 1.f / fmaxf(sqrtf(ss), 1e-12f);
            float S1 = s1 * rn;
            float slab = sl * rn;
            float S2 = s2row[r] * rn * rn;
            float om = 1.f - slab;
            li_acc += om * om * (998.f / 999.f)
                    + ((float)NC - 2.f * S1 + S2) * (1.f / 999.f);
        }
    }

    // Block-reduce loss, single global atomic
    {
        float li = li_acc;
        #pragma unroll
        for (int off = 16; off; off >>= 1)
            li += __shfl_xor_sync(0xffffffffu, li, off);
        if (lane == 0) lsum[w] = li;
        __syncthreads();
        if (t == 0) {
            float tot = 0.f;
            #pragma unroll
            for (int i = 0; i < 8; i++) tot += lsum[i];
            atomicAdd(&g_loss, tot);
        }
    }
    grid_barrier();

    // ---------------- P6: final write ----------------
    if (gtid == 0) out[0] = __ldcg(&g_loss) * (1.f / (float)NROWS);
}

// ---------------------------------------------------------------------------
extern "C" void kernel_launch(void* const* d_in, const int* in_sizes, int n_in,
                              void* d_out, int out_size) {
    const float* emb = (const float*)d_in[0];
    const int* labels = (const int*)d_in[1];
    float* out = (float*)d_out;

    const int smem_bytes = (MROWS * EBP + 128 * MBP) * 4
                         + (256 + 128 + 3 * 256 + 128 + 8) * 4;
    cudaFuncSetAttribute(k_fused, cudaFuncAttributeMaxDynamicSharedMemorySize,
                         smem_bytes);
    k_fused<<<GRID, TPB, smem_bytes>>>(emb, labels, out);
}

// round 15
// speedup vs baseline: 1.0891x; 1.0891x over previous
#include <cuda_runtime.h>
#include <math.h>
#include <stdint.h>

#define NROWS 65536
#define D 256
#define NC 1000
#define NCP 1024
#define MROWS 128
#define TPB 256
#define EBP 132     // Ebf pitch in words (132%32=4 -> conflict-free A frags)
#define MBP 72      // Msbf pitch in words (72%32=8 -> conflict-free B frags)
#define NREP 16     // g_sums replicas
#define MSPLIT 16   // k_M K-splits

// ---------------- device scratch ----------------
__device__ float g_sums[NREP * NC * D];
__device__ float g_counts[NREP * NC];
__device__ float g_chat[NCP * D];
__device__ float g_v[D];
__device__ float g_Msplit[MSPLIT * D * D];     // per-split partial M
__device__ uint32_t g_Mbf[(D / 2) * D];        // packed bf16 pairs: [kpair][n]
__device__ uint32_t g_ebf[NROWS * (D / 2)];    // normalized rows, packed bf16
__device__ float g_loss;

__device__ __forceinline__ uint32_t pack_bf16(float lo, float hi) {
    uint32_t r;
    asm("cvt.rn.bf16x2.f32 %0, %1, %2;" : "=r"(r) : "f"(hi), "f"(lo));
    return r;
}
__device__ __forceinline__ float2 unpack_bf16(uint32_t w) {
    float2 f;
    f.x = __uint_as_float(w << 16);
    f.y = __uint_as_float(w & 0xffff0000u);
    return f;
}
__device__ __forceinline__ void red_v4(float* p, float a, float b, float c, float d) {
    asm volatile("red.global.add.v4.f32 [%0], {%1,%2,%3,%4};"
                 :: "l"(p), "f"(a), "f"(b), "f"(c), "f"(d) : "memory");
}

// ---------------------------------------------------------------------------
__global__ void k_zero() {
    int i = blockIdx.x * 256 + threadIdx.x;   // grid 16384*256
    if (i < NREP * NC * D) g_sums[i] = 0.f;
    if (i < NCP * D) g_chat[i] = 0.f;         // incl. padding rows for k_M
    if (i < NREP * NC) g_counts[i] = 0.f;
    if (i < D) g_v[i] = 0.f;
    if (i == 0) g_loss = 0.f;
}

// ---------------------------------------------------------------------------
// Normalize rows; red.v4 into replicated class sums; persist bf16 rows.
__global__ void k_normacc(const float* __restrict__ emb,
                          const int* __restrict__ labels) {
    int warp = threadIdx.x >> 5, lane = threadIdx.x & 31;
    int row = blockIdx.x * 8 + warp;
    const float* e = emb + (size_t)row * D;

    float4 x0 = *(const float4*)(e + lane * 4);
    float4 x1 = *(const float4*)(e + 128 + lane * 4);
    float ss = x0.x * x0.x + x0.y * x0.y + x0.z * x0.z + x0.w * x0.w
             + x1.x * x1.x + x1.y * x1.y + x1.z * x1.z + x1.w * x1.w;
    #pragma unroll
    for (int off = 16; off; off >>= 1)
        ss += __shfl_xor_sync(0xffffffffu, ss, off);

    float rn = 1.f / fmaxf(sqrtf(ss), 1e-12f);
    float4 n0 = make_float4(x0.x * rn, x0.y * rn, x0.z * rn, x0.w * rn);
    float4 n1 = make_float4(x1.x * rn, x1.y * rn, x1.z * rn, x1.w * rn);

    int lab = labels[row];
    int rep = (row >> 3) & (NREP - 1);
    float* dst = g_sums + ((size_t)rep * NC + lab) * D;
    red_v4(dst + lane * 4,       n0.x, n0.y, n0.z, n0.w);
    red_v4(dst + 128 + lane * 4, n1.x, n1.y, n1.z, n1.w);
    if (lane == 0) atomicAdd(&g_counts[rep * NC + lab], 1.f);

    // persist normalized row packed bf16
    uint2 p0, p1;
    p0.x = pack_bf16(n0.x, n0.y); p0.y = pack_bf16(n0.z, n0.w);
    p1.x = pack_bf16(n1.x, n1.y); p1.y = pack_bf16(n1.z, n1.w);
    uint32_t* er = g_ebf + (size_t)row * (D / 2);
    *(uint2*)(er + lane * 2)      = p0;
    *(uint2*)(er + 64 + lane * 2) = p1;
}

// ---------------------------------------------------------------------------
__global__ void k_centers() {
    int c = blockIdx.x, t = threadIdx.x;
    float cnt = 0.f, s = 0.f;
    #pragma unroll
    for (int rp = 0; rp < NREP; rp++) {
        cnt += g_counts[rp * NC + c];
        s += g_sums[((size_t)rp * NC + c) * D + t];
    }
    float center = s / fmaxf(cnt, 1.f);

    float ss = center * center;
    #pragma unroll
    for (int off = 16; off; off >>= 1)
        ss += __shfl_xor_sync(0xffffffffu, ss, off);
    __shared__ float wsum[8];
    __shared__ float denom_s;
    if ((t & 31) == 0) wsum[t >> 5] = ss;
    __syncthreads();
    if (t == 0) {
        float tot = 0.f;
        #pragma unroll
        for (int w = 0; w < 8; w++) tot += wsum[w];
        denom_s = fmaxf(sqrtf(tot), 1e-8f);
    }
    __syncthreads();
    float ch = center / denom_s;
    g_chat[(size_t)c * D + t] = ch;
    atomicAdd(&g_v[t], ch);
}

// ---------------------------------------------------------------------------
// M partials: each z-split writes its own slice (no atomics).
__global__ __launch_bounds__(256) void k_M() {
    __shared__ float As[16][64];
    __shared__ float Bs[16][64];
    int t = threadIdx.x;
    int tx = t & 15, ty = t >> 4;
    int cb = blockIdx.x * 64;
    int rb = blockIdx.y * 64;
    int z = blockIdx.z;
    int k0 = z * 64;

    float acc[4][4] = {};
    #pragma unroll 1
    for (int kc = 0; kc < 4; kc++) {
        __syncthreads();
        {
            int kk = t >> 4, c4 = (t & 15) << 2;
            const float* src = g_chat + (size_t)(k0 + kc * 16 + kk) * D;
            *(float4*)&As[kk][c4] = *(const float4*)(src + rb + c4);
            *(float4*)&Bs[kk][c4] = *(const float4*)(src + cb + c4);
        }
        __syncthreads();
        #pragma unroll
        for (int kk = 0; kk < 16; kk++) {
            float a[4], b[4];
            *(float4*)a = *(float4*)&As[kk][ty * 4];
            *(float4*)b = *(float4*)&Bs[kk][tx * 4];
            #pragma unroll
            for (int i = 0; i < 4; i++)
                #pragma unroll
                for (int j = 0; j < 4; j++)
                    acc[i][j] += a[i] * b[j];
        }
    }
    float* out = g_Msplit + (size_t)z * D * D;
    #pragma unroll
    for (int i = 0; i < 4; i++)
        *(float4*)(out + (size_t)(rb + ty * 4 + i) * D + cb + tx * 4) =
            *(float4*)acc[i];
}

// ---------------------------------------------------------------------------
// Fold 16 M-splits and pack to bf16 pairs.
__global__ void k_Mpack() {
    int i = blockIdx.x * 256 + threadIdx.x;    // 0..32767
    int kp = i >> 8, n = i & 255;
    float m0 = 0.f, m1 = 0.f;
    #pragma unroll
    for (int z = 0; z < MSPLIT; z++) {
        const float* s = g_Msplit + (size_t)z * D * D;
        m0 += s[(size_t)(2 * kp) * D + n];
        m1 += s[(size_t)(2 * kp + 1) * D + n];
    }
    g_Mbf[i] = pack_bf16(m0, m1);
}

// ---------------------------------------------------------------------------
// Main fused kernel. E tiles come pre-normalized/packed from g_ebf; rows are
// unit-norm so the epilogue needs no norm/rsqrt.
__global__ __launch_bounds__(TPB, 2)
void k_main(const int* __restrict__ labels) {
    extern __shared__ float sh[];
    uint32_t* Ebf  = (uint32_t*)sh;            // 128*EBP = 16896 words
    uint32_t* Msbf = Ebf + MROWS * EBP;        // 128*MBP = 9216 words
    float* vsh   = (float*)(Msbf + 128 * MBP); // 256
    float* s2row = vsh + 256;                  // 128
    float* redB  = s2row + 128;                // 256
    float* redC  = redB + 256;                 // 256
    int*   labsh = (int*)(redC + 256);         // 128
    float* lsum  = (float*)(labsh + 128);      // 8

    int t = threadIdx.x;
    int w = t >> 5, lane = t & 31;
    int g = lane >> 2, j = lane & 3;
    int rbw = (w & 3) * 32;
    int nb = (w >> 2) * 32;
    int row0 = blockIdx.x * MROWS;

    // Load packed E tile: 4096 uint4 slots = 128 rows x 32 slots
    #pragma unroll
    for (int i = 0; i < 16; i++) {
        int idx = t + i * TPB;
        int r = idx >> 5, c4 = (idx & 31) << 2;
        *(uint4*)(Ebf + r * EBP + c4) =
            *(const uint4*)(g_ebf + (size_t)(row0 + r) * (D / 2) + c4);
    }
    if (t < 128) labsh[t] = labels[row0 + t];
    if (t < 128) s2row[t] = 0.f;
    vsh[t] = g_v[t];

    float s2p[4] = {0.f, 0.f, 0.f, 0.f};

    #pragma unroll 1
    for (int dc = 0; dc < 4; dc++) {
        __syncthreads();
        #pragma unroll
        for (int i = 0; i < 8; i++) {
            int idx = t + i * TPB;             // 0..2047 uint4 slots
            int kp = idx >> 4, c4 = (idx & 15) << 2;
            *(uint4*)(Msbf + kp * MBP + c4) =
                *(const uint4*)(g_Mbf + kp * 256 + dc * 64 + c4);
        }
        __syncthreads();

        float acc[2][4][4] = {};
        #pragma unroll 2
        for (int ks = 0; ks < 16; ks++) {
            int kp = ks * 8;
            uint32_t a[2][4];
            #pragma unroll
            for (int mt = 0; mt < 2; mt++) {
                const uint32_t* ar = Ebf + (rbw + mt * 16 + g) * EBP + kp + j;
                a[mt][0] = ar[0];
                a[mt][1] = ar[8 * EBP];
                a[mt][2] = ar[4];
                a[mt][3] = ar[8 * EBP + 4];
            }
            #pragma unroll
            for (int nt = 0; nt < 4; nt++) {
                uint32_t b0 = Msbf[(kp + j) * MBP + nb + nt * 8 + g];
                uint32_t b1 = Msbf[(kp + 4 + j) * MBP + nb + nt * 8 + g];
                #pragma unroll
                for (int mt = 0; mt < 2; mt++) {
                    asm volatile(
                        "mma.sync.aligned.m16n8k16.row.col.f32.bf16.bf16.f32 "
                        "{%0,%1,%2,%3}, {%4,%5,%6,%7}, {%8,%9}, {%0,%1,%2,%3};"
                        : "+f"(acc[mt][nt][0]), "+f"(acc[mt][nt][1]),
                          "+f"(acc[mt][nt][2]), "+f"(acc[mt][nt][3])
                        : "r"(a[mt][0]), "r"(a[mt][1]), "r"(a[mt][2]), "r"(a[mt][3]),
                          "r"(b0), "r"(b1));
                }
            }
        }
        #pragma unroll
        for (int mt = 0; mt < 2; mt++) {
            #pragma unroll
            for (int nt = 0; nt < 4; nt++) {
                int wc = (dc * 64 + nb + nt * 8) / 2 + j;
                int r0 = rbw + mt * 16 + g;
                float2 e0 = unpack_bf16(Ebf[r0 * EBP + wc]);
                float2 e1 = unpack_bf16(Ebf[(r0 + 8) * EBP + wc]);
                s2p[mt * 2 + 0] += acc[mt][nt][0] * e0.x + acc[mt][nt][1] * e0.y;
                s2p[mt * 2 + 1] += acc[mt][nt][2] * e1.x + acc[mt][nt][3] * e1.y;
            }
        }
    }

    #pragma unroll
    for (int i = 0; i < 4; i++) {
        float v = s2p[i];
        v += __shfl_xor_sync(0xffffffffu, v, 1);
        v += __shfl_xor_sync(0xffffffffu, v, 2);
        s2p[i] = v;
    }
    if (j == 0) {
        atomicAdd(&s2row[rbw + g],      s2p[0]);
        atomicAdd(&s2row[rbw + g + 8],  s2p[1]);
        atomicAdd(&s2row[rbw + 16 + g], s2p[2]);
        atomicAdd(&s2row[rbw + 24 + g], s2p[3]);
    }

    // Per-row dots (unit rows): s1 = e.v, sl = e.chat[label]
    {
        int r = t & 127, q = t >> 7;
        const uint32_t* er = Ebf + r * EBP + q * 64;
        const float* vr = vsh + q * 128;
        const float* cr = g_chat + (size_t)labsh[r] * D + q * 128;
        float s1 = 0.f, sl = 0.f;
        #pragma unroll
        for (int m = 0; m < 16; m++) {
            uint4 ew = *(const uint4*)(er + m * 4);
            float2 e0 = unpack_bf16(ew.x), e1 = unpack_bf16(ew.y);
            float2 e2 = unpack_bf16(ew.z), e3 = unpack_bf16(ew.w);
            float4 v0 = *(const float4*)(vr + m * 8);
            float4 v1 = *(const float4*)(vr + m * 8 + 4);
            float4 c0 = *(const float4*)(cr + m * 8);
            float4 c1 = *(const float4*)(cr + m * 8 + 4);
            s1 += e0.x * v0.x + e0.y * v0.y + e1.x * v0.z + e1.y * v0.w
                + e2.x * v1.x + e2.y * v1.y + e3.x * v1.z + e3.y * v1.w;
            sl += e0.x * c0.x + e0.y * c0.y + e1.x * c0.z + e1.y * c0.w
                + e2.x * c1.x + e2.y * c1.y + e3.x * c1.z + e3.y * c1.w;
        }
        redB[q * 128 + r] = s1;
        redC[q * 128 + r] = sl;
    }
    __syncthreads();

    float li = 0.f;
    if (t < 128) {
        int r = t;
        float S1 = redB[r] + redB[128 + r];
        float sl = redC[r] + redC[128 + r];
        float S2 = s2row[r];
        float om = 1.f - sl;
        li = om * om * (998.f / 999.f)
           + ((float)NC - 2.f * S1 + S2) * (1.f / 999.f);
    }
    #pragma unroll
    for (int off = 16; off; off >>= 1)
        li += __shfl_xor_sync(0xffffffffu, li, off);
    if ((t & 31) == 0 && t < 128) lsum[t >> 5] = li;
    __syncthreads();
    if (t == 0) atomicAdd(&g_loss, lsum[0] + lsum[1] + lsum[2] + lsum[3]);
}

// ---------------------------------------------------------------------------
__global__ void k_final(float* out) {
    if (threadIdx.x == 0) out[0] = g_loss * (1.f / (float)NROWS);
}

// ---------------------------------------------------------------------------
extern "C" void kernel_launch(void* const* d_in, const int* in_sizes, int n_in,
                              void* d_out, int out_size) {
    const float* emb = (const float*)d_in[0];
    const int* labels = (const int*)d_in[1];
    float* out = (float*)d_out;

    const int smem_bytes = (MROWS * EBP + 128 * MBP) * 4
                         + (256 + 128 + 2 * 256 + 128 + 8) * 4;
    cudaFuncSetAttribute(k_main, cudaFuncAttributeMaxDynamicSharedMemorySize,
                         smem_bytes);

    k_zero<<<16384, 256>>>();
    k_normacc<<<NROWS / 8, 256>>>(emb, labels);
    k_centers<<<NC, 256>>>();
    k_M<<<dim3(4, 4, MSPLIT), 256>>>();
    k_Mpack<<<128, 256>>>();
    k_main<<<NROWS / MROWS, TPB, smem_bytes>>>(labels);
    k_final<<<1, 32>>>(out);
}

// round 17
// speedup vs baseline: 1.1987x; 1.1006x over previous
#include <cuda_runtime.h>
#include <math.h>
#include <stdint.h>

#define NROWS 65536
#define D 256
#define NC 1000
#define NCP 1024
#define MROWS 128
#define NBLK (NROWS / MROWS)   // 512
#define TPB 256
#define EBP 132     // Ebf pitch in 32-bit words (132%32=4 -> conflict-free)
#define MBP 72      // Msbf pitch in 32-bit words (72%32=8 -> conflict-free)
#define NREP 8      // g_sums replicas

// ---------------- device scratch (static zero-init on load) ----------------
__device__ float g_sums[NREP * NC * D];
__device__ float g_counts[NREP * NC];
__device__ float g_chat[NCP * D];   // rows >= NC never written -> stay zero
__device__ float g_v[D];
__device__ float g_M[D * D];
__device__ float g_loss;
__device__ unsigned int g_done;

__device__ __forceinline__ uint32_t pack_bf16(float lo, float hi) {
    uint32_t r;
    asm("cvt.rn.bf16x2.f32 %0, %1, %2;" : "=r"(r) : "f"(hi), "f"(lo));
    return r;
}
__device__ __forceinline__ float2 unpack_bf16(uint32_t w) {
    float2 f;
    f.x = __uint_as_float(w << 16);
    f.y = __uint_as_float(w & 0xffff0000u);
    return f;
}
__device__ __forceinline__ void red_v4(float* p, float a, float b, float c, float d) {
    asm volatile("red.global.add.v4.f32 [%0], {%1,%2,%3,%4};"
                 :: "l"(p), "f"(a), "f"(b), "f"(c), "f"(d) : "memory");
}

// ---------------------------------------------------------------------------
// Normalize rows; red.v4 into replicated class sums. Also zeroes g_M for the
// k_M accumulation later in this same launch sequence.
__global__ void k_normacc(const float* __restrict__ emb,
                          const int* __restrict__ labels) {
    int gi = blockIdx.x * 256 + threadIdx.x;
    if (gi < D * D) g_M[gi] = 0.f;

    int warp = threadIdx.x >> 5, lane = threadIdx.x & 31;
    int row = blockIdx.x * 8 + warp;
    const float* e = emb + (size_t)row * D;

    float4 x0 = *(const float4*)(e + lane * 4);
    float4 x1 = *(const float4*)(e + 128 + lane * 4);
    float ss = x0.x * x0.x + x0.y * x0.y + x0.z * x0.z + x0.w * x0.w
             + x1.x * x1.x + x1.y * x1.y + x1.z * x1.z + x1.w * x1.w;
    #pragma unroll
    for (int off = 16; off; off >>= 1)
        ss += __shfl_xor_sync(0xffffffffu, ss, off);

    float rn = 1.f / fmaxf(sqrtf(ss), 1e-12f);
    int lab = labels[row];
    int rep = (row >> 3) & (NREP - 1);
    float* dst = g_sums + ((size_t)rep * NC + lab) * D;
    red_v4(dst + lane * 4,       x0.x * rn, x0.y * rn, x0.z * rn, x0.w * rn);
    red_v4(dst + 128 + lane * 4, x1.x * rn, x1.y * rn, x1.z * rn, x1.w * rn);
    if (lane == 0) atomicAdd(&g_counts[rep * NC + lab], 1.f);
}

// ---------------------------------------------------------------------------
__global__ void k_centers() {
    int c = blockIdx.x, t = threadIdx.x;
    float cnt = 0.f, s = 0.f;
    #pragma unroll
    for (int rp = 0; rp < NREP; rp++) {
        cnt += g_counts[rp * NC + c];
        s += g_sums[((size_t)rp * NC + c) * D + t];
    }
    float center = s / fmaxf(cnt, 1.f);

    float ss = center * center;
    #pragma unroll
    for (int off = 16; off; off >>= 1)
        ss += __shfl_xor_sync(0xffffffffu, ss, off);
    __shared__ float wsum[8];
    __shared__ float denom_s;
    if ((t & 31) == 0) wsum[t >> 5] = ss;
    __syncthreads();
    if (t == 0) {
        float tot = 0.f;
        #pragma unroll
        for (int w = 0; w < 8; w++) tot += wsum[w];
        denom_s = fmaxf(sqrtf(tot), 1e-8f);
    }
    __syncthreads();
    float ch = center / denom_s;
    g_chat[(size_t)c * D + t] = ch;
    atomicAdd(&g_v[t], ch);
}

// ---------------------------------------------------------------------------
// M = Chat^T Chat (K=1024 padded). 16 K-splits, atomicAdd epilogue.
__global__ __launch_bounds__(256) void k_M() {
    __shared__ float As[16][64];
    __shared__ float Bs[16][64];
    int t = threadIdx.x;
    int tx = t & 15, ty = t >> 4;
    int cb = blockIdx.x * 64;
    int rb = blockIdx.y * 64;
    int k0 = blockIdx.z * 64;

    float acc[4][4] = {};
    #pragma unroll 1
    for (int kc = 0; kc < 4; kc++) {
        __syncthreads();
        {
            int kk = t >> 4, c4 = (t & 15) << 2;
            const float* src = g_chat + (size_t)(k0 + kc * 16 + kk) * D;
            *(float4*)&As[kk][c4] = *(const float4*)(src + rb + c4);
            *(float4*)&Bs[kk][c4] = *(const float4*)(src + cb + c4);
        }
        __syncthreads();
        #pragma unroll
        for (int kk = 0; kk < 16; kk++) {
            float a[4], b[4];
            *(float4*)a = *(float4*)&As[kk][ty * 4];
            *(float4*)b = *(float4*)&Bs[kk][tx * 4];
            #pragma unroll
            for (int i = 0; i < 4; i++)
                #pragma unroll
                for (int j = 0; j < 4; j++)
                    acc[i][j] += a[i] * b[j];
        }
    }
    #pragma unroll
    for (int i = 0; i < 4; i++)
        #pragma unroll
        for (int j = 0; j < 4; j++)
            atomicAdd(&g_M[(size_t)(rb + ty * 4 + i) * D + cb + tx * 4 + j],
                      acc[i][j]);
}

// ---------------------------------------------------------------------------
// Main fused kernel (proven R6 body) + end-of-kernel scratch cleanup and
// last-block final reduction/output.
__global__ __launch_bounds__(TPB, 2)
void k_main(const float* __restrict__ emb, const int* __restrict__ labels,
            float* __restrict__ out) {
    extern __shared__ float sh[];
    uint32_t* Ebf  = (uint32_t*)sh;            // 128*EBP = 16896 words
    uint32_t* Msbf = Ebf + MROWS * EBP;        // 128*MBP = 9216 words
    float* vsh   = (float*)(Msbf + 128 * MBP); // 256
    float* s2row = vsh + 256;                  // 128
    float* redA  = s2row + 128;                // 256
    float* redB  = redA + 256;                 // 256
    float* redC  = redB + 256;                 // 256
    int*   labsh = (int*)(redC + 256);         // 128
    float* lsum  = (float*)(labsh + 128);      // 8
    __shared__ int is_last;

    int t = threadIdx.x;
    int w = t >> 5, lane = t & 31;
    int g = lane >> 2, j = lane & 3;
    int rbw = (w & 3) * 32;
    int nb = (w >> 2) * 32;
    int row0 = blockIdx.x * MROWS;

    // Load E tile [128 x 256] -> packed bf16 (pairs along K)
    #pragma unroll
    for (int i = 0; i < 32; i++) {
        int idx = t + i * TPB;
        int r = idx >> 6, c = (idx & 63) << 2;
        float4 x = *(const float4*)(emb + (size_t)(row0 + r) * D + c);
        uint2 p;
        p.x = pack_bf16(x.x, x.y);
        p.y = pack_bf16(x.z, x.w);
        *(uint2*)(Ebf + r * EBP + (c >> 1)) = p;
    }
    if (t < 128) labsh[t] = labels[row0 + t];
    if (t < 128) s2row[t] = 0.f;
    vsh[t] = g_v[t];

    float s2p[4] = {0.f, 0.f, 0.f, 0.f};

    #pragma unroll 1
    for (int dc = 0; dc < 4; dc++) {
        __syncthreads();
        // Stage M chunk cols [dc*64, dc*64+64) as packed bf16 [kpair][n]
        #pragma unroll
        for (int i = 0; i < 8; i++) {
            int idx = t + i * TPB;             // 0..2047
            int kp = idx >> 4, c4 = (idx & 15) << 2;
            const float* m0 = g_M + (size_t)(2 * kp) * D + dc * 64 + c4;
            float4 r0 = *(const float4*)m0;
            float4 r1 = *(const float4*)(m0 + D);
            uint4 pw;
            pw.x = pack_bf16(r0.x, r1.x);
            pw.y = pack_bf16(r0.y, r1.y);
            pw.z = pack_bf16(r0.z, r1.z);
            pw.w = pack_bf16(r0.w, r1.w);
            *(uint4*)(Msbf + kp * MBP + c4) = pw;
        }
        __syncthreads();

        float acc[2][4][4] = {};
        #pragma unroll 2
        for (int ks = 0; ks < 16; ks++) {
            int kp = ks * 8;
            uint32_t a[2][4];
            #pragma unroll
            for (int mt = 0; mt < 2; mt++) {
                const uint32_t* ar = Ebf + (rbw + mt * 16 + g) * EBP + kp + j;
                a[mt][0] = ar[0];
                a[mt][1] = ar[8 * EBP];
                a[mt][2] = ar[4];
                a[mt][3] = ar[8 * EBP + 4];
            }
            #pragma unroll
            for (int nt = 0; nt < 4; nt++) {
                uint32_t b0 = Msbf[(kp + j) * MBP + nb + nt * 8 + g];
                uint32_t b1 = Msbf[(kp + 4 + j) * MBP + nb + nt * 8 + g];
                #pragma unroll
                for (int mt = 0; mt < 2; mt++) {
                    asm volatile(
                        "mma.sync.aligned.m16n8k16.row.col.f32.bf16.bf16.f32 "
                        "{%0,%1,%2,%3}, {%4,%5,%6,%7}, {%8,%9}, {%0,%1,%2,%3};"
                        : "+f"(acc[mt][nt][0]), "+f"(acc[mt][nt][1]),
                          "+f"(acc[mt][nt][2]), "+f"(acc[mt][nt][3])
                        : "r"(a[mt][0]), "r"(a[mt][1]), "r"(a[mt][2]), "r"(a[mt][3]),
                          "r"(b0), "r"(b1));
                }
            }
        }
        // Fold T-chunk into s2 partials from bf16 smem E
        #pragma unroll
        for (int mt = 0; mt < 2; mt++) {
            #pragma unroll
            for (int nt = 0; nt < 4; nt++) {
                int wc = (dc * 64 + nb + nt * 8) / 2 + j;
                int r0 = rbw + mt * 16 + g;
                float2 e0 = unpack_bf16(Ebf[r0 * EBP + wc]);
                float2 e1 = unpack_bf16(Ebf[(r0 + 8) * EBP + wc]);
                s2p[mt * 2 + 0] += acc[mt][nt][0] * e0.x + acc[mt][nt][1] * e0.y;
                s2p[mt * 2 + 1] += acc[mt][nt][2] * e1.x + acc[mt][nt][3] * e1.y;
            }
        }
    }

    #pragma unroll
    for (int i = 0; i < 4; i++) {
        float v = s2p[i];
        v += __shfl_xor_sync(0xffffffffu, v, 1);
        v += __shfl_xor_sync(0xffffffffu, v, 2);
        s2p[i] = v;
    }
    if (j == 0) {
        atomicAdd(&s2row[rbw + g],      s2p[0]);
        atomicAdd(&s2row[rbw + g + 8],  s2p[1]);
        atomicAdd(&s2row[rbw + 16 + g], s2p[2]);
        atomicAdd(&s2row[rbw + 24 + g], s2p[3]);
    }

    // Per-row dots from bf16 smem E: ss, e.v, e.chat[label]
    {
        int r = t & 127, q = t >> 7;
        const uint32_t* er = Ebf + r * EBP + q * 64;
        const float* vr = vsh + q * 128;
        const float* cr = g_chat + (size_t)labsh[r] * D + q * 128;
        float ss = 0.f, s1 = 0.f, sl = 0.f;
        #pragma unroll
        for (int m = 0; m < 16; m++) {
            uint4 ew = *(const uint4*)(er + m * 4);
            float2 e0 = unpack_bf16(ew.x), e1 = unpack_bf16(ew.y);
            float2 e2 = unpack_bf16(ew.z), e3 = unpack_bf16(ew.w);
            float4 v0 = *(const float4*)(vr + m * 8);
            float4 v1 = *(const float4*)(vr + m * 8 + 4);
            float4 c0 = *(const float4*)(cr + m * 8);
            float4 c1 = *(const float4*)(cr + m * 8 + 4);
            ss += e0.x * e0.x + e0.y * e0.y + e1.x * e1.x + e1.y * e1.y
                + e2.x * e2.x + e2.y * e2.y + e3.x * e3.x + e3.y * e3.y;
            s1 += e0.x * v0.x + e0.y * v0.y + e1.x * v0.z + e1.y * v0.w
                + e2.x * v1.x + e2.y * v1.y + e3.x * v1.z + e3.y * v1.w;
            sl += e0.x * c0.x + e0.y * c0.y + e1.x * c0.z + e1.y * c0.w
                + e2.x * c1.x + e2.y * c1.y + e3.x * c1.z + e3.y * c1.w;
        }
        redA[q * 128 + r] = ss;
        redB[q * 128 + r] = s1;
        redC[q * 128 + r] = sl;
    }
    __syncthreads();

    float li = 0.f;
    if (t < 128) {
        int r = t;
        float ss = redA[r] + redA[128 + r];
        float s1 = redB[r] + redB[128 + r];
        float sl = redC[r] + redC[128 + r];
        float rn = 1.f / fmaxf(sqrtf(ss), 1e-12f);
        float S1 = s1 * rn;
        float slab = sl * rn;
        float S2 = s2row[r] * rn * rn;
        float om = 1.f - slab;
        li = om * om * (998.f / 999.f)
           + ((float)NC - 2.f * S1 + S2) * (1.f / 999.f);
    }
    #pragma unroll
    for (int off = 16; off; off >>= 1)
        li += __shfl_xor_sync(0xffffffffu, li, off);
    if (lane == 0 && t < 128) lsum[w] = li;
    __syncthreads();
    if (t == 0) atomicAdd(&g_loss, lsum[0] + lsum[1] + lsum[2] + lsum[3]);

    // ---- cleanup for next replay: zero g_sums/g_counts (no reader here) ----
    {
        const float4 z4 = make_float4(0.f, 0.f, 0.f, 0.f);
        int gt = blockIdx.x * TPB + t;
        for (int i = gt; i < NREP * NC * D / 4; i += NBLK * TPB)
            ((float4*)g_sums)[i] = z4;
        for (int i = gt; i < NREP * NC; i += NBLK * TPB)
            g_counts[i] = 0.f;
    }

    // ---- last-block: final output + zero read-shared scratch ----
    __threadfence();
    __syncthreads();
    if (t == 0) {
        unsigned int d = atomicAdd(&g_done, 1u);
        is_last = (d == NBLK - 1u);
    }
    __syncthreads();
    if (is_last) {
        g_v[t] = 0.f;                          // t covers all 256 entries
        if (t == 0) {
            float total = atomicAdd(&g_loss, 0.f);   // L2-coherent read
            out[0] = total * (1.f / (float)NROWS);
            g_loss = 0.f;
            g_done = 0u;
        }
    }
}

// ---------------------------------------------------------------------------
extern "C" void kernel_launch(void* const* d_in, const int* in_sizes, int n_in,
                              void* d_out, int out_size) {
    const float* emb = (const float*)d_in[0];
    const int* labels = (const int*)d_in[1];
    float* out = (float*)d_out;

    const int smem_bytes = (MROWS * EBP + 128 * MBP) * 4
                         + (256 + 128 + 3 * 256 + 128 + 8) * 4;
    cudaFuncSetAttribute(k_main, cudaFuncAttributeMaxDynamicSharedMemorySize,
                         smem_bytes);

    k_normacc<<<NROWS / 8, 256>>>(emb, labels);
    k_centers<<<NC, 256>>>();
    k_M<<<dim3(4, 4, 16), 256>>>();
    k_main<<<NBLK, TPB, smem_bytes>>>(emb, labels, out);
}